// round 1
// baseline (speedup 1.0000x reference)
#include <cuda_runtime.h>
#include <math.h>

#define B 2048
#define N 128
#define D 512
#define BD (B * D)

// 8 MB scratch for cw = content @ cow, rows interleaved: row 2b = text[b]@cow, 2b+1 = img[b]@cow
__device__ float g_cw[2 * B * D];

__device__ __forceinline__ float fast_tanh(float x) {
    float ax = fabsf(x);
    float e = __expf(-2.0f * ax);
    float t = __fdividef(1.0f - e, 1.0f + e);
    return copysignf(t, x);
}

// ---------------------------------------------------------------------------
// Kernel 1: cw[4096, 512] = A[4096, 512] @ cow[512, 512]
// A row r: (r&1)? img[r>>1] : text[r>>1]
// Classic SMEM-tiled SGEMM: BM=BN=64, BK=16, 256 threads, 4x4 microtile.
// ---------------------------------------------------------------------------
__global__ __launch_bounds__(256) void gemm_cw_kernel(
    const float* __restrict__ text,
    const float* __restrict__ img,
    const float* __restrict__ cow)
{
    __shared__ float As[16][64];   // [k][m]
    __shared__ float Bs[16][64];   // [k][n]

    const int tx = threadIdx.x;
    const int block_row = blockIdx.y * 64;
    const int block_col = blockIdx.x * 64;
    const int tr = (tx / 16) * 4;
    const int tc = (tx % 16) * 4;

    float acc[4][4];
#pragma unroll
    for (int i = 0; i < 4; i++)
#pragma unroll
        for (int j = 0; j < 4; j++) acc[i][j] = 0.f;

    for (int k0 = 0; k0 < D; k0 += 16) {
        // Load A tile (64 rows x 16 k): thread t -> row t/4, k-offset (t%4)*4
        {
            int m = tx >> 2;
            int kk = (tx & 3) * 4;
            int r = block_row + m;
            const float* Ap = ((r & 1) ? img : text) + (size_t)(r >> 1) * D + k0 + kk;
            float4 v = *reinterpret_cast<const float4*>(Ap);
            As[kk + 0][m] = v.x;
            As[kk + 1][m] = v.y;
            As[kk + 2][m] = v.z;
            As[kk + 3][m] = v.w;
        }
        // Load B tile (16 k x 64 cols): thread t -> k t/16, col-offset (t%16)*4
        {
            int kk = tx >> 4;
            int c = (tx & 15) * 4;
            float4 v = *reinterpret_cast<const float4*>(cow + (size_t)(k0 + kk) * D + block_col + c);
            *reinterpret_cast<float4*>(&Bs[kk][c]) = v;
        }
        __syncthreads();
#pragma unroll
        for (int k = 0; k < 16; k++) {
            float4 a4 = *reinterpret_cast<const float4*>(&As[k][tr]);
            float4 b4 = *reinterpret_cast<const float4*>(&Bs[k][tc]);
            float a[4] = {a4.x, a4.y, a4.z, a4.w};
            float b[4] = {b4.x, b4.y, b4.z, b4.w};
#pragma unroll
            for (int i = 0; i < 4; i++)
#pragma unroll
                for (int j = 0; j < 4; j++) acc[i][j] = fmaf(a[i], b[j], acc[i][j]);
        }
        __syncthreads();
    }

#pragma unroll
    for (int i = 0; i < 4; i++) {
        float4 v = make_float4(acc[i][0], acc[i][1], acc[i][2], acc[i][3]);
        *reinterpret_cast<float4*>(&g_cw[(size_t)(block_row + tr + i) * D + block_col + tc]) = v;
    }
}

// ---------------------------------------------------------------------------
// Kernel 2: one CTA per sample. 16 warps; warp w handles comment rows
// n = w, w+16, ... < num. Single pass over z does:
//   - co_w[k,n] = tanh(z_n . cw_k)
//   - accA_k += co_w[k,n] * z_n              (for content attention)
//   - logit_n = sum_d tanh(z + co_w0*c0 + co_w1*c1) * W_co  (bias cancels in softmax)
//   - online masked softmax over n + weighted accumulation of z (refine_comment)
// ---------------------------------------------------------------------------
__global__ __launch_bounds__(512) void fuse_kernel(
    const float* __restrict__ text,
    const float* __restrict__ img,
    const float* __restrict__ comment,
    const int*   __restrict__ comment_num,
    const float* __restrict__ W_ca,
    const float* __restrict__ W_co,
    float* __restrict__ out)
{
    const int b = blockIdx.x;
    const int tid = threadIdx.x;
    const int w = tid >> 5;
    const int lane = tid & 31;

    __shared__ float s_cw0[D], s_cw1[D], s_c0[D], s_c1[D], s_Wco[D];
    __shared__ float s_accA0[D], s_accA1[D];
    __shared__ float s_buf[16][D];          // per-warp refine_comment accumulators
    __shared__ float s_m[16], s_s[16], s_alpha[16];
    __shared__ float s_r0[16], s_r1[16];
    __shared__ float s_w01[2];
    __shared__ float s_S;

    s_cw0[tid] = g_cw[(size_t)(2 * b) * D + tid];
    s_cw1[tid] = g_cw[(size_t)(2 * b + 1) * D + tid];
    s_c0[tid]  = text[(size_t)b * D + tid];
    s_c1[tid]  = img[(size_t)b * D + tid];
    s_Wco[tid] = W_co[tid];
    s_accA0[tid] = 0.f;
    s_accA1[tid] = 0.f;
    __syncthreads();

    const int num = comment_num[b];
    const float* zb = comment + (size_t)b * N * D;

    float aA0[16], aA1[16], aC[16];
#pragma unroll
    for (int i = 0; i < 16; i++) { aA0[i] = 0.f; aA1[i] = 0.f; aC[i] = 0.f; }
    float m = -INFINITY, ssum = 0.f;

    for (int n = w; n < num; n += 16) {
        const float4* zr = reinterpret_cast<const float4*>(zb + (size_t)n * D);
        float4 z[4];
#pragma unroll
        for (int j = 0; j < 4; j++) z[j] = zr[lane + 32 * j];

        // dots with cw0, cw1
        float d0 = 0.f, d1 = 0.f;
#pragma unroll
        for (int j = 0; j < 4; j++) {
            int base = (lane + 32 * j) * 4;
            float4 a = *reinterpret_cast<const float4*>(&s_cw0[base]);
            float4 c = *reinterpret_cast<const float4*>(&s_cw1[base]);
            d0 = fmaf(z[j].x, a.x, fmaf(z[j].y, a.y, fmaf(z[j].z, a.z, fmaf(z[j].w, a.w, d0))));
            d1 = fmaf(z[j].x, c.x, fmaf(z[j].y, c.y, fmaf(z[j].z, c.z, fmaf(z[j].w, c.w, d1))));
        }
#pragma unroll
        for (int off = 16; off; off >>= 1) {
            d0 += __shfl_xor_sync(0xffffffffu, d0, off);
            d1 += __shfl_xor_sync(0xffffffffu, d1, off);
        }
        float t0 = fast_tanh(d0);
        float t1 = fast_tanh(d1);

        // accumulate accA, compute zw logit
        float lp = 0.f;
#pragma unroll
        for (int j = 0; j < 4; j++) {
            int base = (lane + 32 * j) * 4;
            float4 c0 = *reinterpret_cast<const float4*>(&s_c0[base]);
            float4 c1 = *reinterpret_cast<const float4*>(&s_c1[base]);
            float4 wv = *reinterpret_cast<const float4*>(&s_Wco[base]);
            float zt;
            zt = fast_tanh(fmaf(t0, c0.x, fmaf(t1, c1.x, z[j].x))); lp = fmaf(zt, wv.x, lp);
            zt = fast_tanh(fmaf(t0, c0.y, fmaf(t1, c1.y, z[j].y))); lp = fmaf(zt, wv.y, lp);
            zt = fast_tanh(fmaf(t0, c0.z, fmaf(t1, c1.z, z[j].z))); lp = fmaf(zt, wv.z, lp);
            zt = fast_tanh(fmaf(t0, c0.w, fmaf(t1, c1.w, z[j].w))); lp = fmaf(zt, wv.w, lp);
            aA0[j * 4 + 0] = fmaf(t0, z[j].x, aA0[j * 4 + 0]);
            aA0[j * 4 + 1] = fmaf(t0, z[j].y, aA0[j * 4 + 1]);
            aA0[j * 4 + 2] = fmaf(t0, z[j].z, aA0[j * 4 + 2]);
            aA0[j * 4 + 3] = fmaf(t0, z[j].w, aA0[j * 4 + 3]);
            aA1[j * 4 + 0] = fmaf(t1, z[j].x, aA1[j * 4 + 0]);
            aA1[j * 4 + 1] = fmaf(t1, z[j].y, aA1[j * 4 + 1]);
            aA1[j * 4 + 2] = fmaf(t1, z[j].z, aA1[j * 4 + 2]);
            aA1[j * 4 + 3] = fmaf(t1, z[j].w, aA1[j * 4 + 3]);
        }
#pragma unroll
        for (int off = 16; off; off >>= 1) lp += __shfl_xor_sync(0xffffffffu, lp, off);

        // online softmax (warp-uniform branch)
        if (lp > m) {
            float corr = __expf(m - lp);   // exp(-inf)=0 on first row
            ssum = fmaf(ssum, corr, 1.f);
#pragma unroll
            for (int j = 0; j < 4; j++) {
                aC[j * 4 + 0] = fmaf(aC[j * 4 + 0], corr, z[j].x);
                aC[j * 4 + 1] = fmaf(aC[j * 4 + 1], corr, z[j].y);
                aC[j * 4 + 2] = fmaf(aC[j * 4 + 2], corr, z[j].z);
                aC[j * 4 + 3] = fmaf(aC[j * 4 + 3], corr, z[j].w);
            }
            m = lp;
        } else {
            float p = __expf(lp - m);
            ssum += p;
#pragma unroll
            for (int j = 0; j < 4; j++) {
                aC[j * 4 + 0] = fmaf(p, z[j].x, aC[j * 4 + 0]);
                aC[j * 4 + 1] = fmaf(p, z[j].y, aC[j * 4 + 1]);
                aC[j * 4 + 2] = fmaf(p, z[j].z, aC[j * 4 + 2]);
                aC[j * 4 + 3] = fmaf(p, z[j].w, aC[j * 4 + 3]);
            }
        }
    }

    // stash warp state
    if (lane == 0) { s_m[w] = m; s_s[w] = ssum; }
#pragma unroll
    for (int j = 0; j < 4; j++) {
        int base = (lane + 32 * j) * 4;
        float4 v = make_float4(aC[j * 4 + 0], aC[j * 4 + 1], aC[j * 4 + 2], aC[j * 4 + 3]);
        *reinterpret_cast<float4*>(&s_buf[w][base]) = v;
        atomicAdd(&s_accA0[base + 0], aA0[j * 4 + 0]);
        atomicAdd(&s_accA0[base + 1], aA0[j * 4 + 1]);
        atomicAdd(&s_accA0[base + 2], aA0[j * 4 + 2]);
        atomicAdd(&s_accA0[base + 3], aA0[j * 4 + 3]);
        atomicAdd(&s_accA1[base + 0], aA1[j * 4 + 0]);
        atomicAdd(&s_accA1[base + 1], aA1[j * 4 + 1]);
        atomicAdd(&s_accA1[base + 2], aA1[j * 4 + 2]);
        atomicAdd(&s_accA1[base + 3], aA1[j * 4 + 3]);
    }
    __syncthreads();

    // combine the 16 online-softmax states (warp 0, lanes 0..15)
    if (w == 0 && lane < 16) {
        float mw = s_m[lane];
        float M = mw;
#pragma unroll
        for (int off = 8; off; off >>= 1) M = fmaxf(M, __shfl_xor_sync(0xffffu, M, off));
        float alpha = (mw == -INFINITY) ? 0.f : __expf(mw - M);
        float Sp = alpha * s_s[lane];
#pragma unroll
        for (int off = 8; off; off >>= 1) Sp += __shfl_xor_sync(0xffffu, Sp, off);
        s_alpha[lane] = alpha;
        if (lane == 0) s_S = Sp;
    }
    __syncthreads();

    // refine_comment[d] = sum_w alpha_w * acc_w[d] / S
    float rc = 0.f;
#pragma unroll
    for (int i = 0; i < 16; i++) rc = fmaf(s_alpha[i], s_buf[i][tid], rc);
    out[BD + (size_t)b * D + tid] = rc * __frcp_rn(s_S);

    // content attention: 2-way softmax (bias cancels)
    float wca = __ldg(&W_ca[tid]);
    float v0 = fast_tanh(s_c0[tid] + s_accA0[tid]) * wca;
    float v1 = fast_tanh(s_c1[tid] + s_accA1[tid]) * wca;
#pragma unroll
    for (int off = 16; off; off >>= 1) {
        v0 += __shfl_xor_sync(0xffffffffu, v0, off);
        v1 += __shfl_xor_sync(0xffffffffu, v1, off);
    }
    if (lane == 0) { s_r0[w] = v0; s_r1[w] = v1; }
    __syncthreads();
    if (tid == 0) {
        float L0 = 0.f, L1 = 0.f;
#pragma unroll
        for (int i = 0; i < 16; i++) { L0 += s_r0[i]; L1 += s_r1[i]; }
        float mm = fmaxf(L0, L1);
        float e0 = __expf(L0 - mm), e1 = __expf(L1 - mm);
        float inv = __frcp_rn(e0 + e1);
        float w0 = e0 * inv, w1 = e1 * inv;
        s_w01[0] = w0; s_w01[1] = w1;
        out[2 * BD + 2 * b + 0] = w0;
        out[2 * BD + 2 * b + 1] = w1;
    }
    __syncthreads();
    out[(size_t)b * D + tid] = fmaf(s_c0[tid], s_w01[0], s_c1[tid] * s_w01[1]);
}

extern "C" void kernel_launch(void* const* d_in, const int* in_sizes, int n_in,
                              void* d_out, int out_size)
{
    const float* text        = (const float*)d_in[0];
    const float* img         = (const float*)d_in[1];
    const float* comment     = (const float*)d_in[2];
    const int*   comment_num = (const int*)d_in[3];
    const float* cow         = (const float*)d_in[4];
    const float* W_ca        = (const float*)d_in[5];
    // d_in[6] = b_ca: cancels in softmax
    const float* W_co        = (const float*)d_in[7];
    // d_in[8] = b_co: cancels in softmax
    float* out = (float*)d_out;

    dim3 g1(D / 64, (2 * B) / 64);
    gemm_cw_kernel<<<g1, 256>>>(text, img, cow);
    fuse_kernel<<<B, 512>>>(text, img, comment, comment_num, W_ca, W_co, out);
}

// round 2
// speedup vs baseline: 1.2175x; 1.2175x over previous
#include <cuda_runtime.h>
#include <math.h>

#define B 2048
#define N 128
#define D 512
#define BD (B * D)
#define NW 12            // warps per CTA in fuse kernel
#define NT (NW * 32)     // 384 threads

// 8 MB scratch for cw = content @ cow, rows interleaved: row 2b = text[b]@cow, 2b+1 = img[b]@cow
__device__ float g_cw[2 * B * D];

__device__ __forceinline__ float tanha(float x) {
    float y;
    asm("tanh.approx.f32 %0, %1;" : "=f"(y) : "f"(x));
    return y;
}

// ---------------------------------------------------------------------------
// Kernel 1: cw[4096, 512] = A[4096, 512] @ cow[512, 512]  (fp32, near FFMA floor)
// ---------------------------------------------------------------------------
__global__ __launch_bounds__(256) void gemm_cw_kernel(
    const float* __restrict__ text,
    const float* __restrict__ img,
    const float* __restrict__ cow)
{
    __shared__ float As[16][64];
    __shared__ float Bs[16][64];

    const int tx = threadIdx.x;
    const int block_row = blockIdx.y * 64;
    const int block_col = blockIdx.x * 64;
    const int tr = (tx / 16) * 4;
    const int tc = (tx % 16) * 4;

    float acc[4][4];
#pragma unroll
    for (int i = 0; i < 4; i++)
#pragma unroll
        for (int j = 0; j < 4; j++) acc[i][j] = 0.f;

    for (int k0 = 0; k0 < D; k0 += 16) {
        {
            int m = tx >> 2;
            int kk = (tx & 3) * 4;
            int r = block_row + m;
            const float* Ap = ((r & 1) ? img : text) + (size_t)(r >> 1) * D + k0 + kk;
            float4 v = *reinterpret_cast<const float4*>(Ap);
            As[kk + 0][m] = v.x;
            As[kk + 1][m] = v.y;
            As[kk + 2][m] = v.z;
            As[kk + 3][m] = v.w;
        }
        {
            int kk = tx >> 4;
            int c = (tx & 15) * 4;
            float4 v = *reinterpret_cast<const float4*>(cow + (size_t)(k0 + kk) * D + block_col + c);
            *reinterpret_cast<float4*>(&Bs[kk][c]) = v;
        }
        __syncthreads();
#pragma unroll
        for (int k = 0; k < 16; k++) {
            float4 a4 = *reinterpret_cast<const float4*>(&As[k][tr]);
            float4 b4 = *reinterpret_cast<const float4*>(&Bs[k][tc]);
            float a[4] = {a4.x, a4.y, a4.z, a4.w};
            float b[4] = {b4.x, b4.y, b4.z, b4.w};
#pragma unroll
            for (int i = 0; i < 4; i++)
#pragma unroll
                for (int j = 0; j < 4; j++) acc[i][j] = fmaf(a[i], b[j], acc[i][j]);
        }
        __syncthreads();
    }

#pragma unroll
    for (int i = 0; i < 4; i++) {
        float4 v = make_float4(acc[i][0], acc[i][1], acc[i][2], acc[i][3]);
        *reinterpret_cast<float4*>(&g_cw[(size_t)(block_row + tr + i) * D + block_col + tc]) = v;
    }
}

// ---------------------------------------------------------------------------
// Kernel 2: one CTA (12 warps) per sample. Warp w handles rows n = w, w+12, ...
// Register-resident c0/c1/Wco slices; double-buffered z prefetch; tanh.approx;
// single ragged pass with online masked softmax.
// ---------------------------------------------------------------------------
__global__ __launch_bounds__(NT, 1) void fuse_kernel(
    const float* __restrict__ text,
    const float* __restrict__ img,
    const float* __restrict__ comment,
    const int*   __restrict__ comment_num,
    const float* __restrict__ W_ca,
    const float* __restrict__ W_co,
    float* __restrict__ out)
{
    const int b = blockIdx.x;
    const int tid = threadIdx.x;
    const int w = tid >> 5;
    const int lane = tid & 31;

    __shared__ float s_cw0[D], s_cw1[D], s_c0[D], s_c1[D];
    __shared__ float s_accA0[D], s_accA1[D];
    __shared__ float s_buf[NW][D];
    __shared__ float s_m[NW], s_s[NW], s_alpha[NW];
    __shared__ float s_w01[2];
    __shared__ float s_S;

    for (int d = tid; d < D; d += NT) {
        s_cw0[d] = g_cw[(size_t)(2 * b) * D + d];
        s_cw1[d] = g_cw[(size_t)(2 * b + 1) * D + d];
        s_c0[d]  = text[(size_t)b * D + d];
        s_c1[d]  = img[(size_t)b * D + d];
        s_accA0[d] = 0.f;
        s_accA1[d] = 0.f;
    }
    __syncthreads();

    // Hoist loop-invariant per-thread slices into registers.
    float4 c0r[4], c1r[4], wr[4];
#pragma unroll
    for (int j = 0; j < 4; j++) {
        int q = lane + 32 * j;
        c0r[j] = reinterpret_cast<const float4*>(s_c0)[q];
        c1r[j] = reinterpret_cast<const float4*>(s_c1)[q];
        wr[j]  = __ldg(&reinterpret_cast<const float4*>(W_co)[q]);
    }

    const int num = comment_num[b];
    const float4* zbase = reinterpret_cast<const float4*>(comment + (size_t)b * N * D);

    float4 aA0[4], aA1[4], aC[4];
#pragma unroll
    for (int j = 0; j < 4; j++) {
        aA0[j] = make_float4(0.f, 0.f, 0.f, 0.f);
        aA1[j] = make_float4(0.f, 0.f, 0.f, 0.f);
        aC[j]  = make_float4(0.f, 0.f, 0.f, 0.f);
    }
    float m = -INFINITY, ssum = 0.f;

    // prefetch first row for this warp
    float4 zb[4];
    if (w < num) {
        const float4* zr = zbase + (size_t)w * (D / 4);
#pragma unroll
        for (int j = 0; j < 4; j++) zb[j] = __ldg(&zr[lane + 32 * j]);
    }

    for (int n = w; n < num; n += NW) {
        float4 zc[4];
#pragma unroll
        for (int j = 0; j < 4; j++) zc[j] = zb[j];

        int nn = n + NW;
        if (nn < num) {
            const float4* zr = zbase + (size_t)nn * (D / 4);
#pragma unroll
            for (int j = 0; j < 4; j++) zb[j] = __ldg(&zr[lane + 32 * j]);
        }

        // dots with cw0, cw1 (SMEM)
        float d0 = 0.f, d1 = 0.f;
#pragma unroll
        for (int j = 0; j < 4; j++) {
            int q = lane + 32 * j;
            float4 a = reinterpret_cast<const float4*>(s_cw0)[q];
            float4 c = reinterpret_cast<const float4*>(s_cw1)[q];
            d0 = fmaf(zc[j].x, a.x, fmaf(zc[j].y, a.y, fmaf(zc[j].z, a.z, fmaf(zc[j].w, a.w, d0))));
            d1 = fmaf(zc[j].x, c.x, fmaf(zc[j].y, c.y, fmaf(zc[j].z, c.z, fmaf(zc[j].w, c.w, d1))));
        }
#pragma unroll
        for (int off = 16; off; off >>= 1) {
            d0 += __shfl_xor_sync(0xffffffffu, d0, off);
            d1 += __shfl_xor_sync(0xffffffffu, d1, off);
        }
        float t0 = tanha(d0);
        float t1 = tanha(d1);

        // accA accumulation + zw logit (all register operands)
        float lp = 0.f;
#pragma unroll
        for (int j = 0; j < 4; j++) {
            float zt;
            zt = tanha(fmaf(t0, c0r[j].x, fmaf(t1, c1r[j].x, zc[j].x))); lp = fmaf(zt, wr[j].x, lp);
            zt = tanha(fmaf(t0, c0r[j].y, fmaf(t1, c1r[j].y, zc[j].y))); lp = fmaf(zt, wr[j].y, lp);
            zt = tanha(fmaf(t0, c0r[j].z, fmaf(t1, c1r[j].z, zc[j].z))); lp = fmaf(zt, wr[j].z, lp);
            zt = tanha(fmaf(t0, c0r[j].w, fmaf(t1, c1r[j].w, zc[j].w))); lp = fmaf(zt, wr[j].w, lp);
            aA0[j].x = fmaf(t0, zc[j].x, aA0[j].x);
            aA0[j].y = fmaf(t0, zc[j].y, aA0[j].y);
            aA0[j].z = fmaf(t0, zc[j].z, aA0[j].z);
            aA0[j].w = fmaf(t0, zc[j].w, aA0[j].w);
            aA1[j].x = fmaf(t1, zc[j].x, aA1[j].x);
            aA1[j].y = fmaf(t1, zc[j].y, aA1[j].y);
            aA1[j].z = fmaf(t1, zc[j].z, aA1[j].z);
            aA1[j].w = fmaf(t1, zc[j].w, aA1[j].w);
        }
#pragma unroll
        for (int off = 16; off; off >>= 1) lp += __shfl_xor_sync(0xffffffffu, lp, off);

        // online softmax (warp-uniform branch)
        if (lp > m) {
            float corr = __expf(m - lp);   // exp(-inf)=0 on first row
            ssum = fmaf(ssum, corr, 1.f);
#pragma unroll
            for (int j = 0; j < 4; j++) {
                aC[j].x = fmaf(aC[j].x, corr, zc[j].x);
                aC[j].y = fmaf(aC[j].y, corr, zc[j].y);
                aC[j].z = fmaf(aC[j].z, corr, zc[j].z);
                aC[j].w = fmaf(aC[j].w, corr, zc[j].w);
            }
            m = lp;
        } else {
            float p = __expf(lp - m);
            ssum += p;
#pragma unroll
            for (int j = 0; j < 4; j++) {
                aC[j].x = fmaf(p, zc[j].x, aC[j].x);
                aC[j].y = fmaf(p, zc[j].y, aC[j].y);
                aC[j].z = fmaf(p, zc[j].z, aC[j].z);
                aC[j].w = fmaf(p, zc[j].w, aC[j].w);
            }
        }
    }

    // stash warp state
    if (lane == 0) { s_m[w] = m; s_s[w] = ssum; }
#pragma unroll
    for (int j = 0; j < 4; j++) {
        int base = (lane + 32 * j) * 4;
        *reinterpret_cast<float4*>(&s_buf[w][base]) = aC[j];
        atomicAdd(&s_accA0[base + 0], aA0[j].x);
        atomicAdd(&s_accA0[base + 1], aA0[j].y);
        atomicAdd(&s_accA0[base + 2], aA0[j].z);
        atomicAdd(&s_accA0[base + 3], aA0[j].w);
        atomicAdd(&s_accA1[base + 0], aA1[j].x);
        atomicAdd(&s_accA1[base + 1], aA1[j].y);
        atomicAdd(&s_accA1[base + 2], aA1[j].z);
        atomicAdd(&s_accA1[base + 3], aA1[j].w);
    }
    __syncthreads();

    // combine the NW online-softmax states (warp 0, lanes 0..15)
    if (w == 0 && lane < 16) {
        float mw = (lane < NW) ? s_m[lane] : -INFINITY;
        float sw = (lane < NW) ? s_s[lane] : 0.f;
        float M = mw;
#pragma unroll
        for (int off = 8; off; off >>= 1) M = fmaxf(M, __shfl_xor_sync(0xffffu, M, off));
        float alpha = (mw == -INFINITY) ? 0.f : __expf(mw - M);
        float Sp = alpha * sw;
#pragma unroll
        for (int off = 8; off; off >>= 1) Sp += __shfl_xor_sync(0xffffu, Sp, off);
        if (lane < NW) s_alpha[lane] = alpha;
        if (lane == 0) s_S = Sp;
    }
    __syncthreads();

    // refine_comment[d] = sum_w alpha_w * acc_w[d] / S
    {
        float invS = __frcp_rn(s_S);
        for (int d = tid; d < D; d += NT) {
            float rc = 0.f;
#pragma unroll
            for (int i = 0; i < NW; i++) rc = fmaf(s_alpha[i], s_buf[i][d], rc);
            out[BD + (size_t)b * D + d] = rc * invS;
        }
    }

    // content attention logits (warp 0 covers all 512 d via its 16-slice)
    if (w == 0) {
        float v0 = 0.f, v1 = 0.f;
#pragma unroll
        for (int j = 0; j < 4; j++) {
            int base = (lane + 32 * j) * 4;
            float4 wa = __ldg(&reinterpret_cast<const float4*>(W_ca)[lane + 32 * j]);
            v0 = fmaf(tanha(c0r[j].x + s_accA0[base + 0]), wa.x, v0);
            v0 = fmaf(tanha(c0r[j].y + s_accA0[base + 1]), wa.y, v0);
            v0 = fmaf(tanha(c0r[j].z + s_accA0[base + 2]), wa.z, v0);
            v0 = fmaf(tanha(c0r[j].w + s_accA0[base + 3]), wa.w, v0);
            v1 = fmaf(tanha(c1r[j].x + s_accA1[base + 0]), wa.x, v1);
            v1 = fmaf(tanha(c1r[j].y + s_accA1[base + 1]), wa.y, v1);
            v1 = fmaf(tanha(c1r[j].z + s_accA1[base + 2]), wa.z, v1);
            v1 = fmaf(tanha(c1r[j].w + s_accA1[base + 3]), wa.w, v1);
        }
#pragma unroll
        for (int off = 16; off; off >>= 1) {
            v0 += __shfl_xor_sync(0xffffffffu, v0, off);
            v1 += __shfl_xor_sync(0xffffffffu, v1, off);
        }
        if (lane == 0) {
            float mm = fmaxf(v0, v1);
            float e0 = __expf(v0 - mm), e1 = __expf(v1 - mm);
            float inv = __frcp_rn(e0 + e1);
            float w0 = e0 * inv, w1 = e1 * inv;
            s_w01[0] = w0; s_w01[1] = w1;
            out[2 * BD + 2 * b + 0] = w0;
            out[2 * BD + 2 * b + 1] = w1;
        }
    }
    __syncthreads();

    {
        float w0 = s_w01[0], w1 = s_w01[1];
        for (int d = tid; d < D; d += NT)
            out[(size_t)b * D + d] = fmaf(s_c0[d], w0, s_c1[d] * w1);
    }
}

extern "C" void kernel_launch(void* const* d_in, const int* in_sizes, int n_in,
                              void* d_out, int out_size)
{
    const float* text        = (const float*)d_in[0];
    const float* img         = (const float*)d_in[1];
    const float* comment     = (const float*)d_in[2];
    const int*   comment_num = (const int*)d_in[3];
    const float* cow         = (const float*)d_in[4];
    const float* W_ca        = (const float*)d_in[5];
    // d_in[6] = b_ca: cancels in softmax
    const float* W_co        = (const float*)d_in[7];
    // d_in[8] = b_co: cancels in softmax
    float* out = (float*)d_out;

    dim3 g1(D / 64, (2 * B) / 64);
    gemm_cw_kernel<<<g1, 256>>>(text, img, cow);
    fuse_kernel<<<B, NT>>>(text, img, comment, comment_num, W_ca, W_co, out);
}